// round 4
// baseline (speedup 1.0000x reference)
#include <cuda_runtime.h>
#include <cuda_bf16.h>
#include <cstdint>

#define D 128
#define MAXNZ 512
#define SWS 132            // sW float stride: bank(4d+4t)%32 -> conflict-free LDS.128
#define GRID_MAX 444       // 3 CTAs/SM * 148 SMs

// ---------------------------------------------------------------------------
// Fused persistent kernel. Each CTA:
//   1) stages W (128x128) into smem once (float4 blit, stride-132 padding)
//   2) for each assigned batch row:
//      a) scan F[uid] (float4), compact nonzeros to smem
//      b) sparse-aggregate agg[d] = sum_j w_j * E[idx_j][d]  (2 k-split halves)
//      c) linear out[r] = agg @ W^T + bias from smem (vectorized, conflict-free)
// ---------------------------------------------------------------------------
__global__ __launch_bounds__(256, 3) void fused_kernel(
    const int*   __restrict__ ids,
    const float* __restrict__ F,
    const float* __restrict__ E,
    const float* __restrict__ W,
    const float* __restrict__ bias,
    float*       __restrict__ out,
    int n_total, int B)
{
    extern __shared__ __align__(16) float sW[];       // [128][SWS]
    __shared__ __align__(16) float s_w[MAXNZ];
    __shared__ int                 s_idx[MAXNZ];
    __shared__ __align__(16) float s_part[2][D];      // aggregate partials (k-split)
    __shared__ __align__(16) float s_lin[2][D];       // linear partials (k-split)
    __shared__ int s_cnt;

    const int tid = threadIdx.x;

    // ---- stage W: straight float4 copy into padded layout ----
    {
        const float4* __restrict__ W4 = (const float4*)W;
        float4* __restrict__ sW4 = (float4*)sW;
#pragma unroll
        for (int t = 0; t < 16; ++t) {
            const int i4 = tid + t * 256;     // 0..4095
            const int dd = i4 >> 5;
            const int c  = i4 & 31;
            sW4[dd * (SWS / 4) + c] = W4[i4];
        }
    }
    // (synced before first use by the post-scan barrier below)

    const int h    = tid >> 7;                 // 0/1: k-half for aggregate
    const int dl   = tid & 127;                // d for aggregate
    const int wid  = tid >> 5;
    const int lane = tid & 31;
    const int lh   = wid >> 2;                 // 0/1: k-half for linear
    const int ld   = lane + 32 * (wid & 3);    // d for linear

    for (int r = blockIdx.x; r < B; r += gridDim.x) {
        if (tid == 0) s_cnt = 0;
        __syncthreads();

        const int uid = ids[r];
        const float* __restrict__ row = F + (size_t)uid * (size_t)n_total;

        // ---- a) scan + compact ----
        if (((n_total & 3) == 0) && ((((uintptr_t)row) & 15) == 0)) {
            const float4* __restrict__ row4 = (const float4*)row;
            const int nvec = n_total >> 2;
            for (int i = tid; i < nvec; i += 256) {
                float4 v = row4[i];
                if (v.x != 0.0f) { int p = atomicAdd(&s_cnt, 1); if (p < MAXNZ) { s_idx[p] = 4*i + 0; s_w[p] = v.x; } }
                if (v.y != 0.0f) { int p = atomicAdd(&s_cnt, 1); if (p < MAXNZ) { s_idx[p] = 4*i + 1; s_w[p] = v.y; } }
                if (v.z != 0.0f) { int p = atomicAdd(&s_cnt, 1); if (p < MAXNZ) { s_idx[p] = 4*i + 2; s_w[p] = v.z; } }
                if (v.w != 0.0f) { int p = atomicAdd(&s_cnt, 1); if (p < MAXNZ) { s_idx[p] = 4*i + 3; s_w[p] = v.w; } }
            }
        } else {
            for (int i = tid; i < n_total; i += 256) {
                float v = row[i];
                if (v != 0.0f) { int p = atomicAdd(&s_cnt, 1); if (p < MAXNZ) { s_idx[p] = i; s_w[p] = v; } }
            }
        }
        __syncthreads();

        // ---- b) sparse aggregate, k-split into two contiguous halves ----
        const int cnt = min(s_cnt, MAXNZ);
        const int j0  = h ? (cnt >> 1) : 0;
        const int j1  = h ? cnt : (cnt >> 1);
        float acc = 0.0f;
        int j = j0;
        for (; j + 8 <= j1; j += 8) {      // unroll-8 -> MLP 8 on L2-resident E
            float e0 = E[(size_t)s_idx[j+0] * D + dl];
            float e1 = E[(size_t)s_idx[j+1] * D + dl];
            float e2 = E[(size_t)s_idx[j+2] * D + dl];
            float e3 = E[(size_t)s_idx[j+3] * D + dl];
            float e4 = E[(size_t)s_idx[j+4] * D + dl];
            float e5 = E[(size_t)s_idx[j+5] * D + dl];
            float e6 = E[(size_t)s_idx[j+6] * D + dl];
            float e7 = E[(size_t)s_idx[j+7] * D + dl];
            acc += s_w[j+0] * e0; acc += s_w[j+1] * e1;
            acc += s_w[j+2] * e2; acc += s_w[j+3] * e3;
            acc += s_w[j+4] * e4; acc += s_w[j+5] * e5;
            acc += s_w[j+6] * e6; acc += s_w[j+7] * e7;
        }
        for (; j < j1; ++j)
            acc += s_w[j] * E[(size_t)s_idx[j] * D + dl];
        s_part[h][dl] = acc;
        __syncthreads();

        // ---- c) linear: out_d = sum_k agg[k] * W[d][k], k-split by lh ----
        {
            const float4* __restrict__ p0 = (const float4*)s_part[0];
            const float4* __restrict__ p1 = (const float4*)s_part[1];
            const float4* __restrict__ wrow = ((const float4*)sW) + ld * (SWS / 4);
            float lacc = 0.0f;
#pragma unroll
            for (int t = 0; t < 16; ++t) {
                const int k4 = lh * 16 + t;
                float4 a0 = p0[k4];
                float4 a1 = p1[k4];
                float4 wv = wrow[k4];            // conflict-free LDS.128
                lacc += (a0.x + a1.x) * wv.x;
                lacc += (a0.y + a1.y) * wv.y;
                lacc += (a0.z + a1.z) * wv.z;
                lacc += (a0.w + a1.w) * wv.w;
            }
            s_lin[lh][ld] = lacc;
        }
        __syncthreads();

        if (tid < D)
            out[(size_t)r * D + tid] = s_lin[0][tid] + s_lin[1][tid] + bias[tid];
        // next iteration's top barrier orders the s_cnt reset
    }
}

extern "C" void kernel_launch(void* const* d_in, const int* in_sizes, int n_in,
                              void* d_out, int out_size)
{
    const int*   ids  = (const int*)  d_in[0];
    const float* F    = (const float*)d_in[1];
    const float* E    = (const float*)d_in[2];
    const float* W    = (const float*)d_in[3];
    const float* bias = (const float*)d_in[4];
    float* out = (float*)d_out;

    const int B       = in_sizes[0];
    const int n_total = in_sizes[2] / D;

    const int smem = D * SWS * (int)sizeof(float);   // 67584 B dynamic (sW)
    cudaFuncSetAttribute(fused_kernel, cudaFuncAttributeMaxDynamicSharedMemorySize, smem);

    int grid = B < GRID_MAX ? B : GRID_MAX;
    fused_kernel<<<grid, 256, smem>>>(ids, F, E, W, bias, out, n_total, B);
}

// round 5
// speedup vs baseline: 1.5431x; 1.5431x over previous
#include <cuda_runtime.h>
#include <cuda_bf16.h>
#include <cstdint>

#define D 128
#define MAXNZ 512
#define BM 8               // batch rows per lin CTA
#define SWS 132            // sW float stride -> conflict-free LDS.128 across d
#define MAXB 4096

__device__ float g_agg[(size_t)MAXB * D];

// ---------------------------------------------------------------------------
// Kernel 1: per-batch-row sparse aggregation (unchanged — near HBM floor).
// ---------------------------------------------------------------------------
__global__ __launch_bounds__(128) void agg_kernel(
    const int* __restrict__ ids,
    const float* __restrict__ F,
    const float* __restrict__ E,
    int n_total,
    float* __restrict__ agg)
{
    __shared__ int   s_idx[MAXNZ];
    __shared__ float s_w[MAXNZ];
    __shared__ int   s_cnt;

    const int tid = threadIdx.x;
    if (tid == 0) s_cnt = 0;
    __syncthreads();

    const int uid = ids[blockIdx.x];
    const float* __restrict__ row = F + (size_t)uid * (size_t)n_total;

    if (((n_total & 3) == 0) && ((((uintptr_t)row) & 15) == 0)) {
        const float4* __restrict__ row4 = (const float4*)row;
        const int nvec = n_total >> 2;
        for (int i = tid; i < nvec; i += 128) {
            float4 v = row4[i];
            if (v.x != 0.0f) { int p = atomicAdd(&s_cnt, 1); if (p < MAXNZ) { s_idx[p] = 4*i + 0; s_w[p] = v.x; } }
            if (v.y != 0.0f) { int p = atomicAdd(&s_cnt, 1); if (p < MAXNZ) { s_idx[p] = 4*i + 1; s_w[p] = v.y; } }
            if (v.z != 0.0f) { int p = atomicAdd(&s_cnt, 1); if (p < MAXNZ) { s_idx[p] = 4*i + 2; s_w[p] = v.z; } }
            if (v.w != 0.0f) { int p = atomicAdd(&s_cnt, 1); if (p < MAXNZ) { s_idx[p] = 4*i + 3; s_w[p] = v.w; } }
        }
    } else {
        for (int i = tid; i < n_total; i += 128) {
            float v = row[i];
            if (v != 0.0f) { int p = atomicAdd(&s_cnt, 1); if (p < MAXNZ) { s_idx[p] = i; s_w[p] = v; } }
        }
    }
    __syncthreads();

    const int cnt = min(s_cnt, MAXNZ);
    const int d = tid;
    float acc = 0.0f;

    int j = 0;
    for (; j + 4 <= cnt; j += 4) {
        const float w0 = s_w[j + 0], w1 = s_w[j + 1], w2 = s_w[j + 2], w3 = s_w[j + 3];
        const float e0 = E[(size_t)s_idx[j + 0] * D + d];
        const float e1 = E[(size_t)s_idx[j + 1] * D + d];
        const float e2 = E[(size_t)s_idx[j + 2] * D + d];
        const float e3 = E[(size_t)s_idx[j + 3] * D + d];
        acc += w0 * e0;
        acc += w1 * e1;
        acc += w2 * e2;
        acc += w3 * e3;
    }
    for (; j < cnt; ++j)
        acc += s_w[j] * E[(size_t)s_idx[j] * D + d];

    agg[(size_t)blockIdx.x * D + d] = acc;
}

// ---------------------------------------------------------------------------
// Kernel 2: out[b][d] = bias[d] + sum_k agg[b][k] * W[d][k]
// BM=8 rows/CTA, grid=256 (2 CTAs/SM -> staging latency overlaps compute),
// 256 threads. Thread (tx,ty): row ty, 4 d-lanes tx+32j.
// Inner loop fully float4: per 4-k chunk = 1 broadcast LDS.128 (agg) +
// 4 conflict-free LDS.128 (W, stride 132) + 16 FMA.
// ---------------------------------------------------------------------------
__global__ __launch_bounds__(256) void lin_kernel(
    const float* __restrict__ agg,
    const float* __restrict__ W,
    const float* __restrict__ bias,
    float* __restrict__ out,
    int B)
{
    extern __shared__ __align__(16) float smem[];
    float* sW = smem;                 // [128][SWS]
    float* sA = smem + D * SWS;       // [BM][128]

    const int tid = threadIdx.x;
    const int tx  = tid & 31;
    const int ty  = tid >> 5;         // 0..7 -> row

    // stage W: float4 blit into padded rows
    {
        const float4* __restrict__ W4 = (const float4*)W;
        float4* __restrict__ sW4 = (float4*)sW;
#pragma unroll
        for (int t = 0; t < 16; ++t) {
            const int i4 = tid + t * 256;     // 0..4095
            const int dd = i4 >> 5;
            const int c  = i4 & 31;
            sW4[dd * (SWS / 4) + c] = W4[i4];
        }
    }

    // stage agg tile (BM*D/4 = 256 float4 -> 1 per thread)
    const int row0 = blockIdx.x * BM;
    {
        const float4* __restrict__ A4 = (const float4*)(agg + (size_t)row0 * D);
        ((float4*)sA)[tid] = A4[tid];
    }
    __syncthreads();

    float acc[4] = {0.f, 0.f, 0.f, 0.f};
    const float4* __restrict__ a4 = ((const float4*)sA) + ty * (D / 4);
    const float4* __restrict__ w4b = (const float4*)sW;

#pragma unroll 8
    for (int k4 = 0; k4 < D / 4; ++k4) {
        const float4 a = a4[k4];                         // warp broadcast
#pragma unroll
        for (int j = 0; j < 4; ++j) {
            const float4 w = w4b[(tx + 32 * j) * (SWS / 4) + k4];  // conflict-free
            acc[j] += a.x * w.x;
            acc[j] += a.y * w.y;
            acc[j] += a.z * w.z;
            acc[j] += a.w * w.w;
        }
    }

    const int r = row0 + ty;
    if (r < B) {
#pragma unroll
        for (int j = 0; j < 4; ++j)
            out[(size_t)r * D + tx + 32 * j] = acc[j] + bias[tx + 32 * j];
    }
}

extern "C" void kernel_launch(void* const* d_in, const int* in_sizes, int n_in,
                              void* d_out, int out_size)
{
    const int*   ids  = (const int*)  d_in[0];
    const float* F    = (const float*)d_in[1];
    const float* E    = (const float*)d_in[2];
    const float* W    = (const float*)d_in[3];
    const float* bias = (const float*)d_in[4];
    float* out = (float*)d_out;

    const int B       = in_sizes[0];
    const int n_total = in_sizes[2] / D;

    float* agg;
    cudaGetSymbolAddress((void**)&agg, g_agg);

    agg_kernel<<<B, 128>>>(ids, F, E, n_total, agg);

    const int smem2 = (D * SWS + BM * D) * (int)sizeof(float);  // ~71.6 KB
    cudaFuncSetAttribute(lin_kernel, cudaFuncAttributeMaxDynamicSharedMemorySize, smem2);
    lin_kernel<<<(B + BM - 1) / BM, 256, smem2>>>(agg, W, bias, out, B);
}

// round 6
// speedup vs baseline: 1.5690x; 1.0168x over previous
#include <cuda_runtime.h>
#include <cuda_bf16.h>
#include <cstdint>

#define D 128
#define MAXNZ 512
#define BM 16              // batch rows per lin CTA
#define SWS 132            // sW float stride -> conflict-free LDS.128 across d
#define MAXB 4096

__device__ float g_agg[(size_t)MAXB * D];

// ---------------------------------------------------------------------------
// Kernel 1: per-batch-row sparse aggregation (near HBM floor).
// F loads use __ldcs (evict-first) so the 83MB stream doesn't thrash L2's
// copy of E (5.2MB) and W.
// ---------------------------------------------------------------------------
__global__ __launch_bounds__(128) void agg_kernel(
    const int* __restrict__ ids,
    const float* __restrict__ F,
    const float* __restrict__ E,
    int n_total,
    float* __restrict__ agg)
{
    __shared__ int   s_idx[MAXNZ];
    __shared__ float s_w[MAXNZ];
    __shared__ int   s_cnt;

    const int tid = threadIdx.x;
    if (tid == 0) s_cnt = 0;
    __syncthreads();

    const int uid = ids[blockIdx.x];
    const float* __restrict__ row = F + (size_t)uid * (size_t)n_total;

    if (((n_total & 3) == 0) && ((((uintptr_t)row) & 15) == 0)) {
        const float4* __restrict__ row4 = (const float4*)row;
        const int nvec = n_total >> 2;
        for (int i = tid; i < nvec; i += 128) {
            float4 v = __ldcs(&row4[i]);
            if (v.x != 0.0f) { int p = atomicAdd(&s_cnt, 1); if (p < MAXNZ) { s_idx[p] = 4*i + 0; s_w[p] = v.x; } }
            if (v.y != 0.0f) { int p = atomicAdd(&s_cnt, 1); if (p < MAXNZ) { s_idx[p] = 4*i + 1; s_w[p] = v.y; } }
            if (v.z != 0.0f) { int p = atomicAdd(&s_cnt, 1); if (p < MAXNZ) { s_idx[p] = 4*i + 2; s_w[p] = v.z; } }
            if (v.w != 0.0f) { int p = atomicAdd(&s_cnt, 1); if (p < MAXNZ) { s_idx[p] = 4*i + 3; s_w[p] = v.w; } }
        }
    } else {
        for (int i = tid; i < n_total; i += 128) {
            float v = __ldcs(&row[i]);
            if (v != 0.0f) { int p = atomicAdd(&s_cnt, 1); if (p < MAXNZ) { s_idx[p] = i; s_w[p] = v; } }
        }
    }
    __syncthreads();

    const int cnt = min(s_cnt, MAXNZ);
    const int d = tid;
    float acc = 0.0f;

    int j = 0;
    for (; j + 4 <= cnt; j += 4) {
        const float w0 = s_w[j + 0], w1 = s_w[j + 1], w2 = s_w[j + 2], w3 = s_w[j + 3];
        const float e0 = E[(size_t)s_idx[j + 0] * D + d];
        const float e1 = E[(size_t)s_idx[j + 1] * D + d];
        const float e2 = E[(size_t)s_idx[j + 2] * D + d];
        const float e3 = E[(size_t)s_idx[j + 3] * D + d];
        acc += w0 * e0;
        acc += w1 * e1;
        acc += w2 * e2;
        acc += w3 * e3;
    }
    for (; j < cnt; ++j)
        acc += s_w[j] * E[(size_t)s_idx[j] * D + d];

    agg[(size_t)blockIdx.x * D + d] = acc;
}

// ---------------------------------------------------------------------------
// Kernel 2: out[b][d] = bias[d] + sum_k agg[b][k] * W[d][k]
// BM=16 rows/CTA, grid=128, 256 threads (8 warps).
// Thread (tx,ty): rows {2ty, 2ty+1}, cols {tx+32j}. Per k4 chunk:
//   2 broadcast LDS.128 (agg) + 4 conflict-free LDS.128 (W, stride 132)
//   + 32 FMA  -> W smem traffic reused across 2 rows (R=2).
// ---------------------------------------------------------------------------
__global__ __launch_bounds__(256) void lin_kernel(
    const float* __restrict__ agg,
    const float* __restrict__ W,
    const float* __restrict__ bias,
    float* __restrict__ out,
    int B)
{
    extern __shared__ __align__(16) float smem[];
    float* sW = smem;                 // [128][SWS]
    float* sA = smem + D * SWS;       // [BM][128]

    const int tid = threadIdx.x;
    const int tx  = tid & 31;
    const int ty  = tid >> 5;         // 0..7 -> row pair

    // stage W: float4 blit into padded rows (16 LDG.128 per thread)
    {
        const float4* __restrict__ W4 = (const float4*)W;
        float4* __restrict__ sW4 = (float4*)sW;
#pragma unroll
        for (int t = 0; t < 16; ++t) {
            const int i4 = tid + t * 256;     // 0..4095
            const int dd = i4 >> 5;
            const int c  = i4 & 31;
            sW4[dd * (SWS / 4) + c] = W4[i4];
        }
    }

    // stage agg tile (16*128/4 = 512 float4 -> 2 per thread)
    const int row0 = blockIdx.x * BM;
    {
        const float4* __restrict__ A4 = (const float4*)(agg + (size_t)row0 * D);
        float4* __restrict__ sA4 = (float4*)sA;
        sA4[tid]       = A4[tid];
        sA4[tid + 256] = A4[tid + 256];
    }
    __syncthreads();

    float acc0[4] = {0.f, 0.f, 0.f, 0.f};
    float acc1[4] = {0.f, 0.f, 0.f, 0.f};
    const float4* __restrict__ a0 = ((const float4*)sA) + (2 * ty + 0) * (D / 4);
    const float4* __restrict__ a1 = ((const float4*)sA) + (2 * ty + 1) * (D / 4);
    const float4* __restrict__ w4b = (const float4*)sW;

#pragma unroll 4
    for (int k4 = 0; k4 < D / 4; ++k4) {
        const float4 va = a0[k4];                        // broadcast, 1 phase
        const float4 vb = a1[k4];
#pragma unroll
        for (int j = 0; j < 4; ++j) {
            const float4 w = w4b[(tx + 32 * j) * (SWS / 4) + k4];  // conflict-free
            acc0[j] += va.x * w.x; acc0[j] += va.y * w.y;
            acc0[j] += va.z * w.z; acc0[j] += va.w * w.w;
            acc1[j] += vb.x * w.x; acc1[j] += vb.y * w.y;
            acc1[j] += vb.z * w.z; acc1[j] += vb.w * w.w;
        }
    }

    const int r0 = row0 + 2 * ty;
    if (r0 + 1 < B) {
#pragma unroll
        for (int j = 0; j < 4; ++j) {
            const float b = bias[tx + 32 * j];
            out[(size_t)(r0 + 0) * D + tx + 32 * j] = acc0[j] + b;
            out[(size_t)(r0 + 1) * D + tx + 32 * j] = acc1[j] + b;
        }
    } else if (r0 < B) {
#pragma unroll
        for (int j = 0; j < 4; ++j)
            out[(size_t)r0 * D + tx + 32 * j] = acc0[j] + bias[tx + 32 * j];
    }
}

extern "C" void kernel_launch(void* const* d_in, const int* in_sizes, int n_in,
                              void* d_out, int out_size)
{
    const int*   ids  = (const int*)  d_in[0];
    const float* F    = (const float*)d_in[1];
    const float* E    = (const float*)d_in[2];
    const float* W    = (const float*)d_in[3];
    const float* bias = (const float*)d_in[4];
    float* out = (float*)d_out;

    const int B       = in_sizes[0];
    const int n_total = in_sizes[2] / D;

    float* agg;
    cudaGetSymbolAddress((void**)&agg, g_agg);

    agg_kernel<<<B, 128>>>(ids, F, E, n_total, agg);

    const int smem2 = (D * SWS + BM * D) * (int)sizeof(float);  // ~75.6 KB
    cudaFuncSetAttribute(lin_kernel, cudaFuncAttributeMaxDynamicSharedMemorySize, smem2);
    lin_kernel<<<(B + BM - 1) / BM, 256, smem2>>>(agg, W, bias, out, B);
}